// round 12
// baseline (speedup 1.0000x reference)
#include <cuda_runtime.h>
#include <cuda_fp16.h>
#include <cstdint>

#define NUM_USERS 50000
#define NUM_ITEMS 50000
#define NUM_NODES (NUM_USERS + NUM_ITEMS)   // 100000
#define EMB_DIM 128
#define NUM_EDGES 2000000
#define TOTAL_ELEMS (NUM_NODES * EMB_DIM)   // 12,800,000 floats
#define TOTAL_VEC8 (TOTAL_ELEMS / 8)        // 1,600,000 uint4-half8 per buffer

#define ELL_CAP 64   // power of 2; P(Poisson(20) > 64) ~ 1e-14

// ---- device scratch (no allocation allowed) ----
// INVARIANTS (maintained every call):
//  * g_cnt all-zero at entry (zero-init at load; FINAL spmm re-zeroes).
//  * g_ell slots >= cnt[r] are NEVER written -> remain zero from module-load
//    zero-init -> {col=0, val=half2(0,0)}: contribute exactly 0. SpMM reads
//    rows rounded up to the warp-pair max, and prefetches meta/gathers up to
//    8 edges past the end; max padded length 48 + 8 = 56 < 64 stays in-row.
__device__ int   g_cnt[NUM_NODES];
__device__ int2  g_ell[(size_t)NUM_NODES * ELL_CAP];   // {col, half2{v,v}}
// fp16 feature buffers: 128 halves per node = 16 uint4 per node
__device__ uint4 g_h0[TOTAL_VEC8];
__device__ uint4 g_h1[TOTAL_VEC8];
__device__ uint4 g_h2[TOTAL_VEC8];

// ---------------------------------------------------------------------------
// fused prologue (independent index ranges, overlapping the two jobs):
//   i < NUM_EDGES/8 : ELL scatter, 8 edges/thread (8 independent atomic
//                     chains in flight); val converted ONCE to half2 {v,v}.
//   i < TOTAL_VEC8  : convert emb (f32) -> h0 (fp16), 8 halves/thread.
// ---------------------------------------------------------------------------
__global__ void k_prologue(const float* __restrict__ emb,
                           const int* __restrict__ rows,
                           const int* __restrict__ cols,
                           const float* __restrict__ vals) {
    int i = blockIdx.x * blockDim.x + threadIdx.x;

    if (i < NUM_EDGES / 8) {             // NUM_EDGES % 8 == 0
        int base = i * 8;
        int4   ra = *(const int4*)  (rows + base);
        int4   rb = *(const int4*)  (rows + base + 4);
        int4   ca = *(const int4*)  (cols + base);
        int4   cb = *(const int4*)  (cols + base + 4);
        float4 va = *(const float4*)(vals + base);
        float4 vb = *(const float4*)(vals + base + 4);

        int p0 = atomicAdd(&g_cnt[ra.x], 1);
        int p1 = atomicAdd(&g_cnt[ra.y], 1);
        int p2 = atomicAdd(&g_cnt[ra.z], 1);
        int p3 = atomicAdd(&g_cnt[ra.w], 1);
        int p4 = atomicAdd(&g_cnt[rb.x], 1);
        int p5 = atomicAdd(&g_cnt[rb.y], 1);
        int p6 = atomicAdd(&g_cnt[rb.z], 1);
        int p7 = atomicAdd(&g_cnt[rb.w], 1);

        __half2 h0 = __float2half2_rn(va.x);
        __half2 h1 = __float2half2_rn(va.y);
        __half2 h2 = __float2half2_rn(va.z);
        __half2 h3 = __float2half2_rn(va.w);
        __half2 h4 = __float2half2_rn(vb.x);
        __half2 h5 = __float2half2_rn(vb.y);
        __half2 h6 = __float2half2_rn(vb.z);
        __half2 h7 = __float2half2_rn(vb.w);

        g_ell[((unsigned)ra.x << 6) + p0] = make_int2(ca.x, *(int*)&h0);
        g_ell[((unsigned)ra.y << 6) + p1] = make_int2(ca.y, *(int*)&h1);
        g_ell[((unsigned)ra.z << 6) + p2] = make_int2(ca.z, *(int*)&h2);
        g_ell[((unsigned)ra.w << 6) + p3] = make_int2(ca.w, *(int*)&h3);
        g_ell[((unsigned)rb.x << 6) + p4] = make_int2(cb.x, *(int*)&h4);
        g_ell[((unsigned)rb.y << 6) + p5] = make_int2(cb.y, *(int*)&h5);
        g_ell[((unsigned)rb.z << 6) + p6] = make_int2(cb.z, *(int*)&h6);
        g_ell[((unsigned)rb.w << 6) + p7] = make_int2(cb.w, *(int*)&h7);
    }

    if (i < TOTAL_VEC8) {
        float4 a = ((const float4*)emb)[i * 2];
        float4 b = ((const float4*)emb)[i * 2 + 1];
        __half2 p0 = __floats2half2_rn(a.x, a.y);
        __half2 p1 = __floats2half2_rn(a.z, a.w);
        __half2 p2 = __floats2half2_rn(b.x, b.y);
        __half2 p3 = __floats2half2_rn(b.z, b.w);
        uint4 packed;
        packed.x = *(unsigned*)&p0;
        packed.y = *(unsigned*)&p1;
        packed.z = *(unsigned*)&p2;
        packed.w = *(unsigned*)&p3;
        g_h0[i] = packed;
    }
}

// ---------------------------------------------------------------------------
// ELL SpMM, HALF-WARP per row, 2-STAGE SOFTWARE PIPELINE:
// while computing iteration i, iteration i+1's 4 gathers and iteration i+2's
// meta are in flight -> steady-state 8 gathers + 2 meta LDGs outstanding per
// warp. Over-reads hit guaranteed-zero meta -> gathers of x row 0 (L1-hot)
// scaled by v=0 -> contribute exactly 0.
// Inner math: HFMA2; f32 flush every iteration (4 edges).
// FINAL=true: out = 0.25*(h0 + h1 + h2 + acc) via streaming f32 store.
// ---------------------------------------------------------------------------
template <bool FINAL>
__global__ void __launch_bounds__(256, 5)
k_spmm(const uint4* __restrict__ x, uint4* __restrict__ y,
       float* __restrict__ out) {
    int tid   = blockIdx.x * blockDim.x + threadIdx.x;
    int wpair = tid >> 5;                 // warp id = row pair id
    int lane  = threadIdx.x & 31;
    int half  = lane >> 4;                // 0: row 2W, 1: row 2W+1
    int hl    = lane & 15;                // lane within half (uint4 index)
    int row   = (wpair << 1) + half;
    if (row >= NUM_NODES) return;

    int n  = __ldg(&g_cnt[row]);
    int no = __shfl_xor_sync(0xFFFFFFFFu, n, 16);
    int nm = n > no ? n : no;
    int pn = (nm + 3) & ~3;               // padded to x4 (pads are zeros)

    const int4* meta = (const int4*)(g_ell + ((size_t)row << 6));

    float2 a0 = make_float2(0.f, 0.f), a1 = make_float2(0.f, 0.f);
    float2 a2 = make_float2(0.f, 0.f), a3 = make_float2(0.f, 0.f);

    // ---- pipeline prologue: iter-0 meta + gathers, iter-1 meta ----
    int4 ma = __ldg(meta);
    int4 mb = __ldg(meta + 1);
    uint4 r0 = __ldg(x + ((unsigned)ma.x << 4) + hl);
    uint4 r1 = __ldg(x + ((unsigned)ma.z << 4) + hl);
    uint4 r2 = __ldg(x + ((unsigned)mb.x << 4) + hl);
    uint4 r3 = __ldg(x + ((unsigned)mb.z << 4) + hl);
    int4 na = __ldg(meta + 2);
    int4 nb = __ldg(meta + 3);

    for (int i = 0; i < pn; i += 4) {
        // issue next iteration's gathers (from na/nb) + meta for i+8
        uint4 s0 = __ldg(x + ((unsigned)na.x << 4) + hl);
        uint4 s1 = __ldg(x + ((unsigned)na.z << 4) + hl);
        uint4 s2 = __ldg(x + ((unsigned)nb.x << 4) + hl);
        uint4 s3 = __ldg(x + ((unsigned)nb.z << 4) + hl);
        int j = i >> 1;
        int4 ta = __ldg(meta + j + 4);
        int4 tb = __ldg(meta + j + 5);

        // compute current iteration from registers
        __half2 q0 = __float2half2_rn(0.f);
        __half2 q1 = q0, q2 = q0, q3 = q0;
        #define EDGE(mv, rv) do { \
            __half2 v = *(__half2*)&(mv); \
            q0 = __hfma2(v, *(__half2*)&(rv).x, q0); \
            q1 = __hfma2(v, *(__half2*)&(rv).y, q1); \
            q2 = __hfma2(v, *(__half2*)&(rv).z, q2); \
            q3 = __hfma2(v, *(__half2*)&(rv).w, q3); \
        } while (0)
        EDGE(ma.y, r0); EDGE(ma.w, r1);
        EDGE(mb.y, r2); EDGE(mb.w, r3);
        #undef EDGE

        float2 f0 = __half22float2(q0);
        float2 f1 = __half22float2(q1);
        float2 f2 = __half22float2(q2);
        float2 f3 = __half22float2(q3);
        a0.x += f0.x; a0.y += f0.y;
        a1.x += f1.x; a1.y += f1.y;
        a2.x += f2.x; a2.y += f2.y;
        a3.x += f3.x; a3.y += f3.y;

        // rotate pipeline registers
        ma = na; mb = nb; na = ta; nb = tb;
        r0 = s0; r1 = s1; r2 = s2; r3 = s3;
    }

    unsigned idx = ((unsigned)row << 4) + hl;   // uint4 index
    if (!FINAL) {
        __half2 p0 = __floats2half2_rn(a0.x, a0.y);
        __half2 p1 = __floats2half2_rn(a1.x, a1.y);
        __half2 p2 = __floats2half2_rn(a2.x, a2.y);
        __half2 p3 = __floats2half2_rn(a3.x, a3.y);
        uint4 packed;
        packed.x = *(unsigned*)&p0;
        packed.y = *(unsigned*)&p1;
        packed.z = *(unsigned*)&p2;
        packed.w = *(unsigned*)&p3;
        y[idx] = packed;
    } else {
        if (hl == 0) g_cnt[row] = 0;      // restore zero invariant
        uint4 h0v = __ldg(&g_h0[idx]);    // fp16 emb copy (L2-warm)
        uint4 h1v = __ldg(&g_h1[idx]);
        uint4 h2v = __ldg(&g_h2[idx]);
        float2 e0 = __half22float2(*(__half2*)&h0v.x);
        float2 e1 = __half22float2(*(__half2*)&h0v.y);
        float2 e2 = __half22float2(*(__half2*)&h0v.z);
        float2 e3 = __half22float2(*(__half2*)&h0v.w);
        float2 b0 = __half22float2(*(__half2*)&h1v.x);
        float2 b1 = __half22float2(*(__half2*)&h1v.y);
        float2 b2 = __half22float2(*(__half2*)&h1v.z);
        float2 b3 = __half22float2(*(__half2*)&h1v.w);
        float2 c0 = __half22float2(*(__half2*)&h2v.x);
        float2 c1 = __half22float2(*(__half2*)&h2v.y);
        float2 c2 = __half22float2(*(__half2*)&h2v.z);
        float2 c3 = __half22float2(*(__half2*)&h2v.w);
        float4 o0, o1;
        o0.x = 0.25f * (e0.x + b0.x + c0.x + a0.x);
        o0.y = 0.25f * (e0.y + b0.y + c0.y + a0.y);
        o0.z = 0.25f * (e1.x + b1.x + c1.x + a1.x);
        o0.w = 0.25f * (e1.y + b1.y + c1.y + a1.y);
        o1.x = 0.25f * (e2.x + b2.x + c2.x + a2.x);
        o1.y = 0.25f * (e2.y + b2.y + c2.y + a2.y);
        o1.z = 0.25f * (e3.x + b3.x + c3.x + a3.x);
        o1.w = 0.25f * (e3.y + b3.y + c3.y + a3.y);
        __stcs((float4*)out + idx * 2,     o0);   // streaming: never re-read
        __stcs((float4*)out + idx * 2 + 1, o1);
    }
}

extern "C" void kernel_launch(void* const* d_in, const int* in_sizes, int n_in,
                              void* d_out, int out_size) {
    const float* emb  = (const float*)d_in[0];
    const int*   rows = (const int*)  d_in[1];
    const int*   cols = (const int*)  d_in[2];
    const float* vals = (const float*)d_in[3];
    float*       out  = (float*)d_out;

    uint4 *h0 = nullptr, *h1 = nullptr, *h2 = nullptr;
    cudaGetSymbolAddress((void**)&h0, g_h0);
    cudaGetSymbolAddress((void**)&h1, g_h1);
    cudaGetSymbolAddress((void**)&h2, g_h2);

    const int TB = 256;
    const int pro_blocks  = (TOTAL_VEC8 + TB - 1) / TB;      // covers both ranges
    const int spmm_blocks = (NUM_NODES * 16 + TB - 1) / TB;  // 16 threads/row

    // fused convert + ELL scatter
    k_prologue<<<pro_blocks, TB>>>(emb, rows, cols, vals);

    // 3 propagation layers; layer 3 fuses the final average into d_out
    k_spmm<false><<<spmm_blocks, TB>>>(h0, h1, nullptr);
    k_spmm<false><<<spmm_blocks, TB>>>(h1, h2, nullptr);
    k_spmm<true ><<<spmm_blocks, TB>>>(h2, nullptr, out);
}

// round 13
// speedup vs baseline: 1.2678x; 1.2678x over previous
#include <cuda_runtime.h>
#include <cuda_fp16.h>
#include <cstdint>

#define NUM_USERS 50000
#define NUM_ITEMS 50000
#define NUM_NODES (NUM_USERS + NUM_ITEMS)   // 100000
#define EMB_DIM 128
#define NUM_EDGES 2000000
#define TOTAL_ELEMS (NUM_NODES * EMB_DIM)   // 12,800,000 floats
#define TOTAL_VEC8 (TOTAL_ELEMS / 8)        // 1,600,000 uint4-half8 per buffer

#define ELL_CAP 64   // power of 2; P(Poisson(20) > 64) ~ 1e-14

// ---- device scratch (no allocation allowed) ----
// INVARIANTS (maintained every call):
//  * g_cnt all-zero at entry (zero-init at load; FINAL spmm re-zeroes).
//  * g_ell slots >= cnt[r] are NEVER written -> remain zero from module-load
//    zero-init -> {col=0, val=half2(0,0)}: contribute exactly 0. SpMM reads
//    rows rounded up to the warp-pair max with no tail handling.
__device__ int   g_cnt[NUM_NODES];
__device__ int2  g_ell[(size_t)NUM_NODES * ELL_CAP];   // {col, half2{v,v}}
// fp16 feature buffers: 128 halves per node = 16 uint4 per node
__device__ uint4 g_h0[TOTAL_VEC8];
__device__ uint4 g_h1[TOTAL_VEC8];
__device__ uint4 g_h2[TOTAL_VEC8];

// ---------------------------------------------------------------------------
// fused prologue (independent index ranges, overlapping the two jobs):
//   i < NUM_EDGES/8 : ELL scatter, 8 edges/thread (8 independent atomic
//                     chains in flight); val converted ONCE to half2 {v,v}.
//   i < TOTAL_VEC8  : convert emb (f32) -> h0 (fp16), 8 halves/thread.
// ---------------------------------------------------------------------------
__global__ void k_prologue(const float* __restrict__ emb,
                           const int* __restrict__ rows,
                           const int* __restrict__ cols,
                           const float* __restrict__ vals) {
    int i = blockIdx.x * blockDim.x + threadIdx.x;

    if (i < NUM_EDGES / 8) {             // NUM_EDGES % 8 == 0
        int base = i * 8;
        int4   ra = *(const int4*)  (rows + base);
        int4   rb = *(const int4*)  (rows + base + 4);
        int4   ca = *(const int4*)  (cols + base);
        int4   cb = *(const int4*)  (cols + base + 4);
        float4 va = *(const float4*)(vals + base);
        float4 vb = *(const float4*)(vals + base + 4);

        int p0 = atomicAdd(&g_cnt[ra.x], 1);
        int p1 = atomicAdd(&g_cnt[ra.y], 1);
        int p2 = atomicAdd(&g_cnt[ra.z], 1);
        int p3 = atomicAdd(&g_cnt[ra.w], 1);
        int p4 = atomicAdd(&g_cnt[rb.x], 1);
        int p5 = atomicAdd(&g_cnt[rb.y], 1);
        int p6 = atomicAdd(&g_cnt[rb.z], 1);
        int p7 = atomicAdd(&g_cnt[rb.w], 1);

        __half2 h0 = __float2half2_rn(va.x);
        __half2 h1 = __float2half2_rn(va.y);
        __half2 h2 = __float2half2_rn(va.z);
        __half2 h3 = __float2half2_rn(va.w);
        __half2 h4 = __float2half2_rn(vb.x);
        __half2 h5 = __float2half2_rn(vb.y);
        __half2 h6 = __float2half2_rn(vb.z);
        __half2 h7 = __float2half2_rn(vb.w);

        g_ell[((unsigned)ra.x << 6) + p0] = make_int2(ca.x, *(int*)&h0);
        g_ell[((unsigned)ra.y << 6) + p1] = make_int2(ca.y, *(int*)&h1);
        g_ell[((unsigned)ra.z << 6) + p2] = make_int2(ca.z, *(int*)&h2);
        g_ell[((unsigned)ra.w << 6) + p3] = make_int2(ca.w, *(int*)&h3);
        g_ell[((unsigned)rb.x << 6) + p4] = make_int2(cb.x, *(int*)&h4);
        g_ell[((unsigned)rb.y << 6) + p5] = make_int2(cb.y, *(int*)&h5);
        g_ell[((unsigned)rb.z << 6) + p6] = make_int2(cb.z, *(int*)&h6);
        g_ell[((unsigned)rb.w << 6) + p7] = make_int2(cb.w, *(int*)&h7);
    }

    if (i < TOTAL_VEC8) {
        float4 a = ((const float4*)emb)[i * 2];
        float4 b = ((const float4*)emb)[i * 2 + 1];
        __half2 p0 = __floats2half2_rn(a.x, a.y);
        __half2 p1 = __floats2half2_rn(a.z, a.w);
        __half2 p2 = __floats2half2_rn(b.x, b.y);
        __half2 p3 = __floats2half2_rn(b.z, b.w);
        uint4 packed;
        packed.x = *(unsigned*)&p0;
        packed.y = *(unsigned*)&p1;
        packed.z = *(unsigned*)&p2;
        packed.w = *(unsigned*)&p3;
        g_h0[i] = packed;
    }
}

// ---------------------------------------------------------------------------
// ELL SpMM, HALF-WARP per row: lanes 0-15 -> row 2W, lanes 16-31 -> row 2W+1.
// Each lane holds 8 halves (uint4). One LDG.128 gathers an edge for BOTH rows
// simultaneously. Loop bound = warp max of both rows' (padded) lengths;
// over-reads hit guaranteed-zero padding -> contribute 0.
// Inner math: HFMA2; f32 flush every iteration (4 edges). Plain body (the
// R8/R10/R11 version) — prefetch/pipeline variants all measured slower.
// TB=128, 12 blocks/SM: finer block granularity reduces end-of-block
// imbalance from Poisson row-length variance.
// FINAL=true: out = 0.25*(h0 + h1 + h2 + acc), streaming f32 store.
// ---------------------------------------------------------------------------
template <bool FINAL>
__global__ void __launch_bounds__(128, 12)
k_spmm(const uint4* __restrict__ x, uint4* __restrict__ y,
       float* __restrict__ out) {
    int tid   = blockIdx.x * blockDim.x + threadIdx.x;
    int wpair = tid >> 5;                 // warp id = row pair id
    int lane  = threadIdx.x & 31;
    int half  = lane >> 4;                // 0: row 2W, 1: row 2W+1
    int hl    = lane & 15;                // lane within half (uint4 index)
    int row   = (wpair << 1) + half;
    if (row >= NUM_NODES) return;

    int n  = __ldg(&g_cnt[row]);
    int no = __shfl_xor_sync(0xFFFFFFFFu, n, 16);
    int nm = n > no ? n : no;
    int pn = (nm + 3) & ~3;               // padded to x4 (pads are zeros)

    const int4* meta = (const int4*)(g_ell + ((size_t)row << 6));

    float2 a0 = make_float2(0.f, 0.f), a1 = make_float2(0.f, 0.f);
    float2 a2 = make_float2(0.f, 0.f), a3 = make_float2(0.f, 0.f);

    for (int i = 0; i < pn; i += 4) {
        int j = i >> 1;
        int4 ma = __ldg(meta + j);        // edges i, i+1 (this half's row)
        int4 mb = __ldg(meta + j + 1);    // edges i+2, i+3

        uint4 r0 = __ldg(x + ((unsigned)ma.x << 4) + hl);
        uint4 r1 = __ldg(x + ((unsigned)ma.z << 4) + hl);
        uint4 r2 = __ldg(x + ((unsigned)mb.x << 4) + hl);
        uint4 r3 = __ldg(x + ((unsigned)mb.z << 4) + hl);

        __half2 s0 = __float2half2_rn(0.f);
        __half2 s1 = s0, s2 = s0, s3 = s0;
        #define EDGE(mv, rv) do { \
            __half2 v = *(__half2*)&(mv); \
            s0 = __hfma2(v, *(__half2*)&(rv).x, s0); \
            s1 = __hfma2(v, *(__half2*)&(rv).y, s1); \
            s2 = __hfma2(v, *(__half2*)&(rv).z, s2); \
            s3 = __hfma2(v, *(__half2*)&(rv).w, s3); \
        } while (0)
        EDGE(ma.y, r0); EDGE(ma.w, r1);
        EDGE(mb.y, r2); EDGE(mb.w, r3);
        #undef EDGE

        float2 f0 = __half22float2(s0);
        float2 f1 = __half22float2(s1);
        float2 f2 = __half22float2(s2);
        float2 f3 = __half22float2(s3);
        a0.x += f0.x; a0.y += f0.y;
        a1.x += f1.x; a1.y += f1.y;
        a2.x += f2.x; a2.y += f2.y;
        a3.x += f3.x; a3.y += f3.y;
    }

    unsigned idx = ((unsigned)row << 4) + hl;   // uint4 index
    if (!FINAL) {
        __half2 p0 = __floats2half2_rn(a0.x, a0.y);
        __half2 p1 = __floats2half2_rn(a1.x, a1.y);
        __half2 p2 = __floats2half2_rn(a2.x, a2.y);
        __half2 p3 = __floats2half2_rn(a3.x, a3.y);
        uint4 packed;
        packed.x = *(unsigned*)&p0;
        packed.y = *(unsigned*)&p1;
        packed.z = *(unsigned*)&p2;
        packed.w = *(unsigned*)&p3;
        y[idx] = packed;
    } else {
        if (hl == 0) g_cnt[row] = 0;      // restore zero invariant
        uint4 h0v = __ldg(&g_h0[idx]);    // fp16 emb copy (L2-warm)
        uint4 h1v = __ldg(&g_h1[idx]);
        uint4 h2v = __ldg(&g_h2[idx]);
        float2 e0 = __half22float2(*(__half2*)&h0v.x);
        float2 e1 = __half22float2(*(__half2*)&h0v.y);
        float2 e2 = __half22float2(*(__half2*)&h0v.z);
        float2 e3 = __half22float2(*(__half2*)&h0v.w);
        float2 b0 = __half22float2(*(__half2*)&h1v.x);
        float2 b1 = __half22float2(*(__half2*)&h1v.y);
        float2 b2 = __half22float2(*(__half2*)&h1v.z);
        float2 b3 = __half22float2(*(__half2*)&h1v.w);
        float2 c0 = __half22float2(*(__half2*)&h2v.x);
        float2 c1 = __half22float2(*(__half2*)&h2v.y);
        float2 c2 = __half22float2(*(__half2*)&h2v.z);
        float2 c3 = __half22float2(*(__half2*)&h2v.w);
        float4 o0, o1;
        o0.x = 0.25f * (e0.x + b0.x + c0.x + a0.x);
        o0.y = 0.25f * (e0.y + b0.y + c0.y + a0.y);
        o0.z = 0.25f * (e1.x + b1.x + c1.x + a1.x);
        o0.w = 0.25f * (e1.y + b1.y + c1.y + a1.y);
        o1.x = 0.25f * (e2.x + b2.x + c2.x + a2.x);
        o1.y = 0.25f * (e2.y + b2.y + c2.y + a2.y);
        o1.z = 0.25f * (e3.x + b3.x + c3.x + a3.x);
        o1.w = 0.25f * (e3.y + b3.y + c3.y + a3.y);
        __stcs((float4*)out + idx * 2,     o0);   // streaming: never re-read
        __stcs((float4*)out + idx * 2 + 1, o1);
    }
}

extern "C" void kernel_launch(void* const* d_in, const int* in_sizes, int n_in,
                              void* d_out, int out_size) {
    const float* emb  = (const float*)d_in[0];
    const int*   rows = (const int*)  d_in[1];
    const int*   cols = (const int*)  d_in[2];
    const float* vals = (const float*)d_in[3];
    float*       out  = (float*)d_out;

    uint4 *h0 = nullptr, *h1 = nullptr, *h2 = nullptr;
    cudaGetSymbolAddress((void**)&h0, g_h0);
    cudaGetSymbolAddress((void**)&h1, g_h1);
    cudaGetSymbolAddress((void**)&h2, g_h2);

    const int PTB = 256;
    const int pro_blocks  = (TOTAL_VEC8 + PTB - 1) / PTB;    // covers both ranges
    const int STB = 128;
    const int spmm_blocks = (NUM_NODES * 16 + STB - 1) / STB; // 16 threads/row

    // fused convert + ELL scatter
    k_prologue<<<pro_blocks, PTB>>>(emb, rows, cols, vals);

    // 3 propagation layers; layer 3 fuses the final average into d_out
    k_spmm<false><<<spmm_blocks, STB>>>(h0, h1, nullptr);
    k_spmm<false><<<spmm_blocks, STB>>>(h1, h2, nullptr);
    k_spmm<true ><<<spmm_blocks, STB>>>(h2, nullptr, out);
}